// round 1
// baseline (speedup 1.0000x reference)
#include <cuda_runtime.h>
#include <math.h>

#define BATCH 64
#define NSZ   512
#define DIM   64
#define BIG   1e10f

// 64 MB scratch for the distance matrix (static device allocation is allowed)
__device__ float g_D[(size_t)BATCH * NSZ * NSZ];

// ---------------------------------------------------------------------------
// Kernel 1: D[b][i][j] = || X[b][i] - Y[b][j] ||_2   (via xn + yn - 2*dot)
// 64x64 tile per block, 256 threads, 4x4 register blocking (strided mapping so
// global stores are coalesced and Ys LDS is conflict-free with pitch 65).
// ---------------------------------------------------------------------------
__global__ __launch_bounds__(256) void dist_kernel(const float* __restrict__ X,
                                                   const float* __restrict__ Y) {
    __shared__ float Xs[64][65];
    __shared__ float Ys[64][65];
    __shared__ float xn[64];
    __shared__ float yn[64];

    const int b  = blockIdx.z;
    const int i0 = blockIdx.y * 64;
    const int j0 = blockIdx.x * 64;
    const int tid = threadIdx.x;

    const float* Xb = X + ((size_t)b * NSZ + i0) * DIM;
    const float* Yb = Y + ((size_t)b * NSZ + j0) * DIM;

    // Load 64x64 tiles (float4 global reads, scalar shared stores)
#pragma unroll
    for (int p = 0; p < 4; p++) {
        int idx = tid + p * 256;
        int row = idx >> 4;
        int c4  = (idx & 15) * 4;
        float4 vx = *(const float4*)(Xb + row * DIM + c4);
        Xs[row][c4 + 0] = vx.x; Xs[row][c4 + 1] = vx.y;
        Xs[row][c4 + 2] = vx.z; Xs[row][c4 + 3] = vx.w;
        float4 vy = *(const float4*)(Yb + row * DIM + c4);
        Ys[row][c4 + 0] = vy.x; Ys[row][c4 + 1] = vy.y;
        Ys[row][c4 + 2] = vy.z; Ys[row][c4 + 3] = vy.w;
    }
    __syncthreads();

    const int tx = tid & 15;   // column group
    const int ty = tid >> 4;   // row group

    float acc[4][4];
#pragma unroll
    for (int u = 0; u < 4; u++)
#pragma unroll
        for (int v = 0; v < 4; v++) acc[u][v] = 0.0f;

#pragma unroll
    for (int k = 0; k < DIM; k++) {
        float av[4], bv[4];
#pragma unroll
        for (int u = 0; u < 4; u++) av[u] = Xs[ty + 16 * u][k];
#pragma unroll
        for (int v = 0; v < 4; v++) bv[v] = Ys[tx + 16 * v][k];
#pragma unroll
        for (int u = 0; u < 4; u++)
#pragma unroll
            for (int v = 0; v < 4; v++) acc[u][v] += av[u] * bv[v];
    }

    // Row norms (cooperative)
    if (tid < 64) {
        float s = 0.0f;
#pragma unroll
        for (int k = 0; k < DIM; k++) { float t = Xs[tid][k]; s += t * t; }
        xn[tid] = s;
    } else if (tid < 128) {
        int r = tid - 64;
        float s = 0.0f;
#pragma unroll
        for (int k = 0; k < DIM; k++) { float t = Ys[r][k]; s += t * t; }
        yn[r] = s;
    }
    __syncthreads();

    float* Dbp = g_D + (size_t)b * NSZ * NSZ;
#pragma unroll
    for (int u = 0; u < 4; u++) {
        int li = ty + 16 * u;
        float xnv = xn[li];
#pragma unroll
        for (int v = 0; v < 4; v++) {
            int lj = tx + 16 * v;
            float d2 = xnv + yn[lj] - 2.0f * acc[u][v];
            Dbp[(size_t)(i0 + li) * NSZ + (j0 + lj)] = sqrtf(fmaxf(d2, 0.0f));
        }
    }
}

// ---------------------------------------------------------------------------
// Kernel 2: soft-DTW DP. One block per batch, 512 threads (thread j-1 owns
// column j). Anti-diagonal wavefront with 3 rotating R buffers. D values are
// staged 16 diagonals at a time into shared memory with coalesced global
// reads (warp-per-row, 16 consecutive floats) and conflict-free diagonal
// shared writes (lane stride 513).
// ---------------------------------------------------------------------------
__global__ __launch_bounds__(512) void dp_kernel(float* __restrict__ out) {
    __shared__ float sh[16][NSZ];       // sh[t][c] = D[kk0+t - c][c]
    __shared__ float Rb[3][NSZ + 1];    // rotating anti-diagonals of R

    const int b   = blockIdx.x;
    const float* Db = g_D + (size_t)b * NSZ * NSZ;
    const int tid = threadIdx.x;

    // init boundary-safe fill
    for (int q = tid; q <= NSZ; q += 512) {
        Rb[0][q] = BIG; Rb[1][q] = BIG; Rb[2][q] = BIG;
    }
    if (tid == 0) Rb[0][0] = 0.0f;   // R[0][0]

    const int warp = tid >> 5;
    const int lane = tid & 31;
    const int sub  = lane >> 4;      // 0/1: which row of the pair
    const int l    = lane & 15;      // diagonal offset t within chunk
    const int j    = tid + 1;        // DP column 1..512

    for (int chunk = 0; chunk < 64; chunk++) {
        const int kk0 = chunk << 4;                  // D-diagonal base (i-1)+(j-1)
        const int rlo = max(0, kk0 - (NSZ - 1));
        const int rhi = min(NSZ - 1, kk0 + 15);

        __syncthreads();  // previous chunk fully consumed before overwriting sh
        for (int r = rlo + warp * 2 + sub; r <= rhi; r += 32) {
            int c = kk0 - r + l;     // t = l
            if (c >= 0 && c < NSZ) sh[l][c] = Db[r * NSZ + c];
        }
        __syncthreads();  // sh ready

        for (int t = 0; t < 16; t++) {
            const int k = kk0 + t + 2;      // R diagonal index (i + j)
            if (k > 2 * NSZ) break;

            float*       cur = Rb[k % 3];
            const float* p1  = Rb[(k + 2) % 3];   // diag k-1
            const float* p2  = Rb[(k + 1) % 3];   // diag k-2

            if (tid == 0) cur[0] = BIG;               // R[k][0]
            if (tid == 1 && k <= NSZ) cur[k] = BIG;   // R[0][k]

            const int i = k - j;
            if (i >= 1 && i <= NSZ) {
                float a  = p2[j - 1];   // diag neighbor R[i-1][j-1]
                float up = p1[j];       // R[i-1][j]
                float lf = p1[j - 1];   // R[i][j-1]
                float d  = sh[t][tid];  // D[i-1][j-1]
                float m  = fminf(a, fminf(up, lf));
                float s  = __expf(m - a) + __expf(m - up) + __expf(m - lf);
                cur[j] = d + m - __logf(s);
            }
            __syncthreads();
        }
    }

    if (tid == 0) out[b] = Rb[(2 * NSZ) % 3][NSZ];  // R[N][N]
}

// ---------------------------------------------------------------------------
extern "C" void kernel_launch(void* const* d_in, const int* in_sizes, int n_in,
                              void* d_out, int out_size) {
    const float* X = (const float*)d_in[0];
    const float* Y = (const float*)d_in[1];
    float* out = (float*)d_out;

    dist_kernel<<<dim3(NSZ / 64, NSZ / 64, BATCH), 256>>>(X, Y);
    dp_kernel<<<BATCH, 512>>>(out);
}